// round 5
// baseline (speedup 1.0000x reference)
#include <cuda_runtime.h>
#include <cuda_fp16.h>
#include <math.h>

// ---------------- problem-size constants ----------------
#define MAXN 100000
#define MAXE 1200000
#define F_IN  64
#define F_HID 64
#define F_OUT 16
#define SCAN_B 256

// ---------------- device scratch (zero at load; re-zeroed at end of agg2) ----
__device__ __half g_y_h[MAXN * F_HID];   // x @ W1, fp16
__device__ __half g_z_h[MAXN * F_OUT];   // h @ W2, fp16
__device__ int    g_deg[MAXN];           // out-degree by row (for dinv)
__device__ int    g_cnt[MAXN];           // in-degree by col (CSR counts)
__device__ float  g_dinv[MAXN];
__device__ int    g_start[MAXN];         // CSR row_ptr
__device__ int    g_cursor[MAXN];        // fill cursors
__device__ int    g_total;               // global CSR allocation cursor
__device__ int2   g_edge[MAXE];          // packed (src, coef bits), bucketed by col

// ---------------- kernels ----------------

// Histogram both endpoints in one pass. Assumes g_deg/g_cnt are zero on entry.
__global__ void hist_kernel(const int* __restrict__ ei, int E) {
    int e = blockIdx.x * blockDim.x + threadIdx.x;
    if (e < E) {
        atomicAdd(&g_deg[ei[e]], 1);
        atomicAdd(&g_cnt[ei[E + e]], 1);
    }
}

// One-kernel CSR allocation: block-local inclusive scan of cnt, single global
// atomicAdd per block for the base, plus dinv computation.
__global__ __launch_bounds__(SCAN_B) void alloc_kernel(int N) {
    __shared__ int s[SCAN_B];
    __shared__ int base_sm;
    int t = threadIdx.x;
    int i = blockIdx.x * SCAN_B + t;
    int v = (i < N) ? g_cnt[i] : 0;
    s[t] = v;
    if (i < N) g_dinv[i] = rsqrtf((float)(g_deg[i] + 1));
    __syncthreads();
    for (int off = 1; off < SCAN_B; off <<= 1) {
        int u = (t >= off) ? s[t - off] : 0;
        __syncthreads();
        s[t] += u;
        __syncthreads();
    }
    if (t == SCAN_B - 1) base_sm = atomicAdd(&g_total, s[t]);
    __syncthreads();
    if (i < N) {
        int st = base_sm + s[t] - v;   // block base + local exclusive scan
        g_start[i] = st;
        g_cursor[i] = st;
    }
}

// Fused: CSR fill (first FB blocks) + gemm1 y = x @ W1 (remaining blocks).
__global__ __launch_bounds__(256) void fill_gemm_kernel(const int* __restrict__ ei, int E,
                                                        const float* __restrict__ x,
                                                        const float* __restrict__ W,
                                                        int N, int FB) {
    __shared__ float Ws[64 * 64];
    __shared__ float xs[16 * 64];
    int tid = threadIdx.x;

    if (blockIdx.x < FB) {
        // ---- fill part ----
        int e = blockIdx.x * 256 + tid;
        if (e < E) {
            int r = ei[e];
            int c = ei[E + e];
            float coef = g_dinv[r] * g_dinv[c];
            int pos = atomicAdd(&g_cursor[c], 1);
            g_edge[pos] = make_int2(r, __float_as_int(coef));
        }
        return;
    }

    // ---- gemm1 part ----
    int bid = blockIdx.x - FB;
    int tx = tid & 63;          // output column
    int ty = tid >> 6;          // 0..3

    for (int i = tid; i < 64 * 64; i += 256) Ws[i] = W[i];

    int row0 = bid * 16;
    {
        int r  = tid >> 4;
        int cc = tid & 15;
        int gr = row0 + r;
        float4 v = (gr < N) ? reinterpret_cast<const float4*>(x)[(size_t)gr * 16 + cc]
                            : make_float4(0.f, 0.f, 0.f, 0.f);
        reinterpret_cast<float4*>(xs)[r * 16 + cc] = v;
    }
    __syncthreads();

    float acc[4] = {0.f, 0.f, 0.f, 0.f};
#pragma unroll
    for (int k = 0; k < 64; k++) {
        float w = Ws[k * 64 + tx];
#pragma unroll
        for (int r = 0; r < 4; r++) acc[r] += xs[(ty * 4 + r) * 64 + k] * w;
    }
#pragma unroll
    for (int r = 0; r < 4; r++) {
        float other = __shfl_xor_sync(0xffffffffu, acc[r], 1);
        int gr = row0 + ty * 4 + r;
        if ((tx & 1) == 0 && gr < N) {
            __half2 hv = __floats2half2_rn(acc[r], other);
            reinterpret_cast<__half2*>(g_y_h)[(size_t)gr * 32 + (tx >> 1)] = hv;
        }
    }
}

// Fused: aggr1 (CSR gather of fp16 rows) + self loop + bias + relu -> h (smem)
//        -> z = h @ W2 -> fp16. One warp per node; unrolled x2 (8 rows in flight).
__global__ __launch_bounds__(256) void agg1_kernel(const float* __restrict__ b1,
                                                   const float* __restrict__ W2,
                                                   int N) {
    __shared__ float W2s[64 * 16];
    __shared__ float h_sm[8][64];
    int tid = threadIdx.x;
    for (int i = tid; i < 64 * 16; i += 256) W2s[i] = W2[i];
    __syncthreads();

    int warp = (blockIdx.x * blockDim.x + tid) >> 5;
    if (warp >= N) return;
    int lane = tid & 31;
    int w = tid >> 5;

    int start = g_start[warp];
    int cnt = g_cnt[warp];
    int slot = lane >> 3;     // 0..3 neighbor slot
    int q = lane & 7;         // uint4 (8-half) chunk within 128B row

    float a[8];
#pragma unroll
    for (int i = 0; i < 8; i++) a[i] = 0.f;

    const uint4* yrows = reinterpret_cast<const uint4*>(g_y_h);
    int j = slot;
    for (; j + 4 < cnt; j += 8) {
        int2 r0 = g_edge[start + j];
        int2 r1 = g_edge[start + j + 4];
        float c0 = __int_as_float(r0.y);
        float c1 = __int_as_float(r1.y);
        uint4 v0 = yrows[(size_t)r0.x * 8 + q];
        uint4 v1 = yrows[(size_t)r1.x * 8 + q];
        float2 f;
        f = __half22float2(*reinterpret_cast<__half2*>(&v0.x)); a[0] += c0 * f.x; a[1] += c0 * f.y;
        f = __half22float2(*reinterpret_cast<__half2*>(&v0.y)); a[2] += c0 * f.x; a[3] += c0 * f.y;
        f = __half22float2(*reinterpret_cast<__half2*>(&v0.z)); a[4] += c0 * f.x; a[5] += c0 * f.y;
        f = __half22float2(*reinterpret_cast<__half2*>(&v0.w)); a[6] += c0 * f.x; a[7] += c0 * f.y;
        f = __half22float2(*reinterpret_cast<__half2*>(&v1.x)); a[0] += c1 * f.x; a[1] += c1 * f.y;
        f = __half22float2(*reinterpret_cast<__half2*>(&v1.y)); a[2] += c1 * f.x; a[3] += c1 * f.y;
        f = __half22float2(*reinterpret_cast<__half2*>(&v1.z)); a[4] += c1 * f.x; a[5] += c1 * f.y;
        f = __half22float2(*reinterpret_cast<__half2*>(&v1.w)); a[6] += c1 * f.x; a[7] += c1 * f.y;
    }
    if (j < cnt) {
        int2 r0 = g_edge[start + j];
        float c0 = __int_as_float(r0.y);
        uint4 v0 = yrows[(size_t)r0.x * 8 + q];
        float2 f;
        f = __half22float2(*reinterpret_cast<__half2*>(&v0.x)); a[0] += c0 * f.x; a[1] += c0 * f.y;
        f = __half22float2(*reinterpret_cast<__half2*>(&v0.y)); a[2] += c0 * f.x; a[3] += c0 * f.y;
        f = __half22float2(*reinterpret_cast<__half2*>(&v0.z)); a[4] += c0 * f.x; a[5] += c0 * f.y;
        f = __half22float2(*reinterpret_cast<__half2*>(&v0.w)); a[6] += c0 * f.x; a[7] += c0 * f.y;
    }
    // reduce across the 4 slots
#pragma unroll
    for (int i = 0; i < 8; i++) {
        a[i] += __shfl_xor_sync(0xffffffffu, a[i], 8);
        a[i] += __shfl_xor_sync(0xffffffffu, a[i], 16);
    }

    if (lane < 8) {
        float di = g_dinv[warp];
        float s = di * di;
        uint4 yv = yrows[(size_t)warp * 8 + q];
        float2 y0 = __half22float2(*reinterpret_cast<__half2*>(&yv.x));
        float2 y1 = __half22float2(*reinterpret_cast<__half2*>(&yv.y));
        float2 y2 = __half22float2(*reinterpret_cast<__half2*>(&yv.z));
        float2 y3 = __half22float2(*reinterpret_cast<__half2*>(&yv.w));
        float4 bb0 = reinterpret_cast<const float4*>(b1)[q * 2];
        float4 bb1 = reinterpret_cast<const float4*>(b1)[q * 2 + 1];
        float4 h0, h1;
        h0.x = fmaxf(a[0] + s * y0.x + bb0.x, 0.f);
        h0.y = fmaxf(a[1] + s * y0.y + bb0.y, 0.f);
        h0.z = fmaxf(a[2] + s * y1.x + bb0.z, 0.f);
        h0.w = fmaxf(a[3] + s * y1.y + bb0.w, 0.f);
        h1.x = fmaxf(a[4] + s * y2.x + bb1.x, 0.f);
        h1.y = fmaxf(a[5] + s * y2.y + bb1.y, 0.f);
        h1.z = fmaxf(a[6] + s * y3.x + bb1.z, 0.f);
        h1.w = fmaxf(a[7] + s * y3.y + bb1.w, 0.f);
        reinterpret_cast<float4*>(h_sm[w])[q * 2]     = h0;
        reinterpret_cast<float4*>(h_sm[w])[q * 2 + 1] = h1;
    }
    __syncwarp();

    // z[warp] = h @ W2  (64 -> 16), lanes 0..15 each compute one output
    float accz = 0.f;
    if (lane < 16) {
#pragma unroll
        for (int k = 0; k < 64; k++) accz += h_sm[w][k] * W2s[k * 16 + lane];
    }
    float otherz = __shfl_xor_sync(0xffffffffu, accz, 1);
    if (lane < 16 && (lane & 1) == 0) {
        __half2 hz = __floats2half2_rn(accz, otherz);
        reinterpret_cast<__half2*>(g_z_h)[(size_t)warp * 8 + (lane >> 1)] = hz;
    }
}

// Fused: aggr2 (CSR gather of fp16 rows) + self loop + bias + log_softmax -> out.
// Also re-zeroes g_deg/g_cnt/g_total for the next graph replay.
__global__ __launch_bounds__(256) void agg2_kernel(const float* __restrict__ b2,
                                                   float* __restrict__ out, int N) {
    int tid = threadIdx.x;
    int warp = (blockIdx.x * blockDim.x + tid) >> 5;
    if (warp >= N) return;
    int lane = tid & 31;

    int start = g_start[warp];
    int cnt = g_cnt[warp];
    __syncwarp();
    // re-zero state for next invocation (values already read by all lanes)
    if (lane == 0) { g_deg[warp] = 0; g_cnt[warp] = 0; }
    if (warp == 0 && lane == 1) g_total = 0;

    int slot = lane >> 2;    // 0..7 neighbor slot
    int q = lane & 3;        // uint2 (4-half) chunk within 32B row

    float a[4];
#pragma unroll
    for (int i = 0; i < 4; i++) a[i] = 0.f;

    const uint2* zrows = reinterpret_cast<const uint2*>(g_z_h);
    for (int j = slot; j < cnt; j += 8) {
        int2 rec = g_edge[start + j];
        float coef = __int_as_float(rec.y);
        uint2 v = zrows[(size_t)rec.x * 4 + q];
        float2 f0 = __half22float2(*reinterpret_cast<__half2*>(&v.x));
        float2 f1 = __half22float2(*reinterpret_cast<__half2*>(&v.y));
        a[0] += coef * f0.x;  a[1] += coef * f0.y;
        a[2] += coef * f1.x;  a[3] += coef * f1.y;
    }
#pragma unroll
    for (int i = 0; i < 4; i++) {
        a[i] += __shfl_xor_sync(0xffffffffu, a[i], 4);
        a[i] += __shfl_xor_sync(0xffffffffu, a[i], 8);
        a[i] += __shfl_xor_sync(0xffffffffu, a[i], 16);
    }

    float di = g_dinv[warp];
    float s = di * di;
    uint2 zv = zrows[(size_t)warp * 4 + q];
    float2 z0 = __half22float2(*reinterpret_cast<__half2*>(&zv.x));
    float2 z1 = __half22float2(*reinterpret_cast<__half2*>(&zv.y));
    float4 bb = reinterpret_cast<const float4*>(b2)[q];
    float4 l;
    l.x = a[0] + s * z0.x + bb.x;
    l.y = a[1] + s * z0.y + bb.y;
    l.z = a[2] + s * z1.x + bb.z;
    l.w = a[3] + s * z1.y + bb.w;

    float m4 = fmaxf(fmaxf(l.x, l.y), fmaxf(l.z, l.w));
    m4 = fmaxf(m4, __shfl_xor_sync(0xffffffffu, m4, 1));
    m4 = fmaxf(m4, __shfl_xor_sync(0xffffffffu, m4, 2));
    float se = __expf(l.x - m4) + __expf(l.y - m4) + __expf(l.z - m4) + __expf(l.w - m4);
    se += __shfl_xor_sync(0xffffffffu, se, 1);
    se += __shfl_xor_sync(0xffffffffu, se, 2);
    float lse = m4 + __logf(se);

    if (lane < 4) {
        float4 o;
        o.x = l.x - lse;
        o.y = l.y - lse;
        o.z = l.z - lse;
        o.w = l.w - lse;
        reinterpret_cast<float4*>(out)[(size_t)warp * 4 + q] = o;
    }
}

// ---------------- launch ----------------
extern "C" void kernel_launch(void* const* d_in, const int* in_sizes, int n_in,
                              void* d_out, int out_size) {
    const float* x  = (const float*)d_in[0];
    const int*   ei = (const int*)d_in[1];   // int32 (JAX x64 disabled)
    const float* W1 = (const float*)d_in[2];
    const float* b1 = (const float*)d_in[3];
    const float* W2 = (const float*)d_in[4];
    const float* b2 = (const float*)d_in[5];
    float*       out = (float*)d_out;

    int N = in_sizes[0] / F_IN;
    int E = in_sizes[1] / 2;
    const int TB = 256;

    hist_kernel<<<(E + TB - 1) / TB, TB>>>(ei, E);
    alloc_kernel<<<(N + SCAN_B - 1) / SCAN_B, SCAN_B>>>(N);

    int FB = (E + TB - 1) / TB;          // fill blocks
    int GB = (N + 15) / 16;              // gemm blocks
    fill_gemm_kernel<<<FB + GB, TB>>>(ei, E, x, W1, N, FB);

    long long a1_threads = (long long)N * 32;
    agg1_kernel<<<(unsigned)((a1_threads + TB - 1) / TB), TB>>>(b1, W2, N);

    long long a2_threads = (long long)N * 32;
    agg2_kernel<<<(unsigned)((a2_threads + TB - 1) / TB), TB>>>(b2, out, N);
}